// round 10
// baseline (speedup 1.0000x reference)
#include <cuda_runtime.h>
#include <cstdint>

// Problem dims
#define SEQ_L   2048
#define DMODEL  768
#define NHEAD   12
#define DHEAD   64
#define FFDIM   3072
#define VOCAB   50257
#define NLAYER  4

// ---------------------------------------------------------------------------
// Device-global scratch (no allocations allowed)
// ---------------------------------------------------------------------------
__device__ float g_x  [SEQ_L * DMODEL];
__device__ float g_h  [SEQ_L * DMODEL];
__device__ float g_q  [SEQ_L * DMODEL];
__device__ float g_k  [SEQ_L * DMODEL];
__device__ float g_v  [SEQ_L * DMODEL];
__device__ float g_att[SEQ_L * DMODEL];
__device__ float g_ffn[SEQ_L * FFDIM];

// ---------------------------------------------------------------------------
// Helpers
// ---------------------------------------------------------------------------
__device__ __forceinline__ float warp_reduce_sum(float v) {
#pragma unroll
    for (int o = 16; o > 0; o >>= 1) v += __shfl_xor_sync(0xffffffffu, v, o);
    return v;
}
__device__ __forceinline__ float gelu_f(float x) {
    float x3 = x * x * x;
    return 0.5f * x * (1.0f + tanhf(0.7978845608028654f * (x + 0.044715f * x3)));
}
__device__ __forceinline__ float to_tf32(float x) {
    float y;
    asm("cvt.rna.tf32.f32 %0, %1;" : "=f"(y) : "f"(x));
    return y;
}
__device__ __forceinline__ uint32_t smem_u32(const void* p) {
    uint32_t a;
    asm("{ .reg .u64 t; cvta.to.shared.u64 t, %1; cvt.u32.u64 %0, t; }"
        : "=r"(a) : "l"(p));
    return a;
}
__device__ __forceinline__ void ldmat_x4(uint32_t& r0, uint32_t& r1,
                                         uint32_t& r2, uint32_t& r3,
                                         uint32_t addr) {
    asm volatile("ldmatrix.sync.aligned.m8n8.x4.shared.b16 {%0,%1,%2,%3}, [%4];"
                 : "=r"(r0), "=r"(r1), "=r"(r2), "=r"(r3) : "r"(addr));
}
__device__ __forceinline__ void mma_tf32(float* c, const uint32_t* a,
                                         const uint32_t* b) {
    asm volatile(
        "mma.sync.aligned.m16n8k8.row.col.f32.tf32.tf32.f32 "
        "{%0,%1,%2,%3},{%4,%5,%6,%7},{%8,%9},{%0,%1,%2,%3};"
        : "+f"(c[0]), "+f"(c[1]), "+f"(c[2]), "+f"(c[3])
        : "r"(a[0]), "r"(a[1]), "r"(a[2]), "r"(a[3]), "r"(b[0]), "r"(b[1]));
}

// ---------------------------------------------------------------------------
// Embedding
// ---------------------------------------------------------------------------
__global__ void embed_kernel(const int* __restrict__ tokens,
                             const float* __restrict__ embed,
                             const float* __restrict__ pos,
                             float* __restrict__ x) {
    int l = blockIdx.x;
    int t = tokens[l];
    const float* er = embed + (size_t)t * DMODEL;
    const float* pr = pos + (size_t)l * DMODEL;
    float* xr = x + (size_t)l * DMODEL;
    for (int d = threadIdx.x; d < DMODEL; d += blockDim.x)
        xr[d] = er[d] + pr[d];
}

// ---------------------------------------------------------------------------
// LayerNorm
// ---------------------------------------------------------------------------
__global__ void ln_kernel(const float* __restrict__ x,
                          const float* __restrict__ gamma,
                          float* __restrict__ out) {
    int l = blockIdx.x;
    const float* row = x + (size_t)l * DMODEL;
    __shared__ float sb_s[8];
    __shared__ float sb_ss[8];
    __shared__ float s_mean, s_rstd;

    float s = 0.f, ss = 0.f;
    for (int d = threadIdx.x; d < DMODEL; d += blockDim.x) {
        float v = row[d];
        s += v; ss += v * v;
    }
    s = warp_reduce_sum(s);
    ss = warp_reduce_sum(ss);
    int warp = threadIdx.x >> 5;
    if ((threadIdx.x & 31) == 0) { sb_s[warp] = s; sb_ss[warp] = ss; }
    __syncthreads();
    if (threadIdx.x == 0) {
        float ts = 0.f, tss = 0.f;
        for (int i = 0; i < 8; i++) { ts += sb_s[i]; tss += sb_ss[i]; }
        float mean = ts * (1.0f / DMODEL);
        float var = tss * (1.0f / DMODEL) - mean * mean;
        s_mean = mean;
        s_rstd = rsqrtf(var + 1e-6f);
    }
    __syncthreads();
    float mean = s_mean, rstd = s_rstd;
    float* o = out + (size_t)l * DMODEL;
    for (int d = threadIdx.x; d < DMODEL; d += blockDim.x)
        o[d] = (row[d] - mean) * rstd * gamma[d];
}

// ---------------------------------------------------------------------------
// Flash attention (validated R4, unchanged)
// ---------------------------------------------------------------------------
#define ALD 68

__global__ __launch_bounds__(128) void flash_attn(const float* __restrict__ q,
                                                  const float* __restrict__ k,
                                                  const float* __restrict__ v,
                                                  float* __restrict__ o) {
    const int qb = 31 - blockIdx.x;
    const int h = blockIdx.y;
    const int tid = threadIdx.x;
    const int lane = tid & 31;
    const int warp = tid >> 5;

    __shared__ float sA[64 * ALD];
    __shared__ float sVt[64 * ALD];
    const uint32_t sAu = smem_u32(sA);
    const uint32_t sVu = smem_u32(sVt);

    const int lr = lane & 7;
    const int sel = lane >> 3;
    const int arof = (sel & 1) ? 8 : 0;
    const int acof = (sel & 2) ? 4 : 0;
    const int brof = (sel & 2) ? 8 : 0;
    const int bcof = (sel & 1) ? 4 : 0;

    {
        const float* qp = q + (size_t)(qb * 64) * DMODEL + h * DHEAD;
#pragma unroll
        for (int i = 0; i < 8; i++) {
            int qi = tid + i * 128;
            int row = qi >> 4, c4 = (qi & 15) << 2;
            float4 vq = *(const float4*)(qp + (size_t)row * DMODEL + c4);
            vq.x = to_tf32(vq.x); vq.y = to_tf32(vq.y);
            vq.z = to_tf32(vq.z); vq.w = to_tf32(vq.w);
            *(float4*)(sA + row * ALD + c4) = vq;
        }
    }
    __syncthreads();
    uint32_t qF[8][4];
#pragma unroll
    for (int kk = 0; kk < 8; kk++) {
        uint32_t ad = sAu + ((warp * 16 + lr + arof) * ALD + kk * 8 + acof) * 4;
        ldmat_x4(qF[kk][0], qF[kk][1], qF[kk][2], qF[kk][3], ad);
    }

    float m0 = -1e30f, m1 = -1e30f, l0 = 0.f, l1 = 0.f;
    float oacc[8][4];
#pragma unroll
    for (int nt = 0; nt < 8; nt++)
#pragma unroll
        for (int c = 0; c < 4; c++) oacc[nt][c] = 0.f;

    const int ntiles = qb + 1;
    for (int t = 0; t < ntiles; t++) {
        const float* kp = k + (size_t)(t * 64) * DMODEL + h * DHEAD;
        const float* vp = v + (size_t)(t * 64) * DMODEL + h * DHEAD;
        float4 kreg[8];
#pragma unroll
        for (int i = 0; i < 8; i++) {
            int qi = tid + i * 128;
            int row = qi >> 4, c4 = (qi & 15) << 2;
            kreg[i] = *(const float4*)(kp + (size_t)row * DMODEL + c4);
        }
        float4 vreg[2][4];
#pragma unroll
        for (int ii = 0; ii < 2; ii++) {
            int tile = tid + ii * 128;
            int ks = tile >> 4, ds = tile & 15;
#pragma unroll
            for (int r = 0; r < 4; r++)
                vreg[ii][r] = *(const float4*)(vp + (size_t)(ks * 4 + r) * DMODEL + ds * 4);
        }

        __syncthreads();

#pragma unroll
        for (int i = 0; i < 8; i++) {
            int qi = tid + i * 128;
            int row = qi >> 4, c4 = (qi & 15) << 2;
            float4 vk = kreg[i];
            vk.x = to_tf32(vk.x); vk.y = to_tf32(vk.y);
            vk.z = to_tf32(vk.z); vk.w = to_tf32(vk.w);
            *(float4*)(sA + row * ALD + c4) = vk;
        }
#pragma unroll
        for (int ii = 0; ii < 2; ii++) {
            int tile = tid + ii * 128;
            int ks = tile >> 4, ds = tile & 15;
            float4 r0 = vreg[ii][0], r1 = vreg[ii][1];
            float4 r2 = vreg[ii][2], r3 = vreg[ii][3];
            float4 t0 = make_float4(to_tf32(r0.x), to_tf32(r1.x), to_tf32(r2.x), to_tf32(r3.x));
            float4 t1 = make_float4(to_tf32(r0.y), to_tf32(r1.y), to_tf32(r2.y), to_tf32(r3.y));
            float4 t2 = make_float4(to_tf32(r0.z), to_tf32(r1.z), to_tf32(r2.z), to_tf32(r3.z));
            float4 t3 = make_float4(to_tf32(r0.w), to_tf32(r1.w), to_tf32(r2.w), to_tf32(r3.w));
            *(float4*)(sVt + (ds * 4 + 0) * ALD + ks * 4) = t0;
            *(float4*)(sVt + (ds * 4 + 1) * ALD + ks * 4) = t1;
            *(float4*)(sVt + (ds * 4 + 2) * ALD + ks * 4) = t2;
            *(float4*)(sVt + (ds * 4 + 3) * ALD + ks * 4) = t3;
        }
        __syncthreads();

        float sacc[8][4];
#pragma unroll
        for (int nt = 0; nt < 8; nt++)
#pragma unroll
            for (int c = 0; c < 4; c++) sacc[nt][c] = 0.f;
#pragma unroll
        for (int kk = 0; kk < 8; kk++) {
            uint32_t bF[8][2];
#pragma unroll
            for (int nt2 = 0; nt2 < 4; nt2++) {
                uint32_t bd = sAu + ((nt2 * 16 + lr + brof) * ALD + kk * 8 + bcof) * 4;
                uint32_t b0, b1, b2, b3;
                ldmat_x4(b0, b1, b2, b3, bd);
                bF[2 * nt2][0] = b0;     bF[2 * nt2][1] = b1;
                bF[2 * nt2 + 1][0] = b2; bF[2 * nt2 + 1][1] = b3;
            }
#pragma unroll
            for (int nt = 0; nt < 8; nt++)
                mma_tf32(sacc[nt], qF[kk], bF[nt]);
        }

        if (t == qb) {
            int r0 = warp * 16 + (lane >> 2);
#pragma unroll
            for (int nt = 0; nt < 8; nt++) {
                int kl = nt * 8 + ((lane & 3) << 1);
                if (kl > r0)         sacc[nt][0] = -1e30f;
                if (kl + 1 > r0)     sacc[nt][1] = -1e30f;
                if (kl > r0 + 8)     sacc[nt][2] = -1e30f;
                if (kl + 1 > r0 + 8) sacc[nt][3] = -1e30f;
            }
        }

        float tm0 = -1e30f, tm1 = -1e30f;
#pragma unroll
        for (int nt = 0; nt < 8; nt++) {
            tm0 = fmaxf(tm0, fmaxf(sacc[nt][0], sacc[nt][1]));
            tm1 = fmaxf(tm1, fmaxf(sacc[nt][2], sacc[nt][3]));
        }
        tm0 = fmaxf(tm0, __shfl_xor_sync(0xffffffffu, tm0, 1));
        tm0 = fmaxf(tm0, __shfl_xor_sync(0xffffffffu, tm0, 2));
        tm1 = fmaxf(tm1, __shfl_xor_sync(0xffffffffu, tm1, 1));
        tm1 = fmaxf(tm1, __shfl_xor_sync(0xffffffffu, tm1, 2));
        float nm0 = fmaxf(m0, tm0), nm1 = fmaxf(m1, tm1);
        float sc0 = __expf(m0 - nm0), sc1 = __expf(m1 - nm1);
        m0 = nm0; m1 = nm1;

        float p[8][4];
        float sum0 = 0.f, sum1 = 0.f;
#pragma unroll
        for (int nt = 0; nt < 8; nt++) {
            p[nt][0] = __expf(sacc[nt][0] - nm0);
            p[nt][1] = __expf(sacc[nt][1] - nm0);
            p[nt][2] = __expf(sacc[nt][2] - nm1);
            p[nt][3] = __expf(sacc[nt][3] - nm1);
            sum0 += p[nt][0] + p[nt][1];
            sum1 += p[nt][2] + p[nt][3];
        }
        sum0 += __shfl_xor_sync(0xffffffffu, sum0, 1);
        sum0 += __shfl_xor_sync(0xffffffffu, sum0, 2);
        sum1 += __shfl_xor_sync(0xffffffffu, sum1, 1);
        sum1 += __shfl_xor_sync(0xffffffffu, sum1, 2);
        l0 = l0 * sc0 + sum0;
        l1 = l1 * sc1 + sum1;
#pragma unroll
        for (int nt = 0; nt < 8; nt++) {
            oacc[nt][0] *= sc0; oacc[nt][1] *= sc0;
            oacc[nt][2] *= sc1; oacc[nt][3] *= sc1;
        }

        __syncthreads();

        {
            int r0 = warp * 16 + (lane >> 2);
            int cb = (lane & 3) << 1;
#pragma unroll
            for (int nt = 0; nt < 8; nt++) {
                int col = nt * 8 + cb;
                *(float2*)(sA + r0 * ALD + col) =
                    make_float2(to_tf32(p[nt][0]), to_tf32(p[nt][1]));
                *(float2*)(sA + (r0 + 8) * ALD + col) =
                    make_float2(to_tf32(p[nt][2]), to_tf32(p[nt][3]));
            }
        }
        __syncwarp();

#pragma unroll
        for (int kk = 0; kk < 8; kk++) {
            uint32_t aP[4];
            uint32_t ad = sAu + ((warp * 16 + lr + arof) * ALD + kk * 8 + acof) * 4;
            ldmat_x4(aP[0], aP[1], aP[2], aP[3], ad);
            uint32_t bF[8][2];
#pragma unroll
            for (int nt2 = 0; nt2 < 4; nt2++) {
                uint32_t bd = sVu + ((nt2 * 16 + lr + brof) * ALD + kk * 8 + bcof) * 4;
                uint32_t b0, b1, b2, b3;
                ldmat_x4(b0, b1, b2, b3, bd);
                bF[2 * nt2][0] = b0;     bF[2 * nt2][1] = b1;
                bF[2 * nt2 + 1][0] = b2; bF[2 * nt2 + 1][1] = b3;
            }
#pragma unroll
            for (int nt = 0; nt < 8; nt++)
                mma_tf32(oacc[nt], aP, bF[nt]);
        }
    }

    float inv0 = 1.0f / l0, inv1 = 1.0f / l1;
    int row0 = qb * 64 + warp * 16 + (lane >> 2);
    int cb = h * DHEAD + ((lane & 3) << 1);
#pragma unroll
    for (int nt = 0; nt < 8; nt++) {
        int col = cb + nt * 8;
        *(float2*)(o + (size_t)row0 * DMODEL + col) =
            make_float2(oacc[nt][0] * inv0, oacc[nt][1] * inv0);
        *(float2*)(o + (size_t)(row0 + 8) * DMODEL + col) =
            make_float2(oacc[nt][2] * inv1, oacc[nt][3] * inv1);
    }
}

// ---------------------------------------------------------------------------
// Narrow TF32 GEMM (R4, validated): 128 threads, tile 128x128, BK=16.
// Used for Wo / W2 (N=768 -> 96 blocks keeps the machine busier than wide).
// ---------------------------------------------------------------------------
#define LDW 20
#define SMEM_FLOATS (4 * 128 * LDW)

template <bool RES, bool GELU_>
__global__ __launch_bounds__(128, 2) void gemm_narrow(const float* __restrict__ A,
                                                      const float* __restrict__ B,
                                                      float* __restrict__ C,
                                                      const float* __restrict__ R,
                                                      int N, int K, float alpha) {
    __shared__ float smem[SMEM_FLOATS];
    const int tid = threadIdx.x;
    const int lane = tid & 31;
    const int warp = tid >> 5;
    const int wm = (warp & 1) * 64;
    const int wn = (warp >> 1) * 64;
    const int bm = blockIdx.y * 128;
    const int bn = blockIdx.x * 128;

    float acc[4][8][4];
#pragma unroll
    for (int i = 0; i < 4; i++)
#pragma unroll
        for (int j = 0; j < 8; j++)
#pragma unroll
            for (int t = 0; t < 4; t++) acc[i][j][t] = 0.f;

    const uint32_t sbase = smem_u32(smem);
    float4 ra[4], rb[4];

    auto load_gl = [&](int k0) {
#pragma unroll
        for (int i = 0; i < 4; i++) {
            int qidx = tid + i * 128;
            int row = qidx >> 2, kq = (qidx & 3) << 2;
            ra[i] = *(const float4*)(A + (size_t)(bm + row) * K + k0 + kq);
            int kr = qidx >> 5, nq = (qidx & 31) << 2;
            rb[i] = *(const float4*)(B + (size_t)(k0 + kr) * N + bn + nq);
        }
    };
    auto stage = [&](int buf) {
        float* sA = smem + buf * (128 * LDW);
        float* sB = smem + 2 * (128 * LDW) + buf * (128 * LDW);
#pragma unroll
        for (int i = 0; i < 4; i++) {
            int qidx = tid + i * 128;
            int row = qidx >> 2, kq = (qidx & 3) << 2;
            float4 va;
            va.x = to_tf32(ra[i].x); va.y = to_tf32(ra[i].y);
            va.z = to_tf32(ra[i].z); va.w = to_tf32(ra[i].w);
            *(float4*)(sA + row * LDW + kq) = va;
            int kr = qidx >> 5, nq = (qidx & 31) << 2;
            sB[(nq + 0) * LDW + kr] = to_tf32(rb[i].x);
            sB[(nq + 1) * LDW + kr] = to_tf32(rb[i].y);
            sB[(nq + 2) * LDW + kr] = to_tf32(rb[i].z);
            sB[(nq + 3) * LDW + kr] = to_tf32(rb[i].w);
        }
    };

    const int nit = K >> 4;
    load_gl(0);
    stage(0);
    __syncthreads();

    const int lr = lane & 7;
    const int sel = lane >> 3;
    const int arof = (sel & 1) ? 8 : 0;
    const int acof = (sel & 2) ? 4 : 0;
    const int brof = (sel & 2) ? 8 : 0;
    const int bcof = (sel & 1) ? 4 : 0;

    for (int it = 0; it < nit; ++it) {
        int cur = it & 1;
        if (it + 1 < nit) load_gl((it + 1) << 4);

        uint32_t aU = sbase + (cur * (128 * LDW)) * 4;
        uint32_t bU = sbase + ((2 + cur) * (128 * LDW)) * 4;

#pragma unroll
        for (int kk8 = 0; kk8 < 2; ++kk8) {
            int kk = kk8 << 3;
            uint32_t aF[4][4], bF[8][2];
#pragma unroll
            for (int mt = 0; mt < 4; mt++) {
                uint32_t ad = aU + ((wm + mt * 16 + lr + arof) * LDW + kk + acof) * 4;
                ldmat_x4(aF[mt][0], aF[mt][1], aF[mt][2], aF[mt][3], ad);
            }
#pragma unroll
            for (int nt2 = 0; nt2 < 4; nt2++) {
                uint32_t bd = bU + ((wn + nt2 * 16 + lr + brof) * LDW + kk + bcof) * 4;
                uint32_t q0, q1, q2, q3;
                ldmat_x4(q0, q1, q2, q3, bd);
                bF[2 * nt2][0] = q0;     bF[2 * nt2][1] = q1;
                bF[2 * nt2 + 1][0] = q2; bF[2 * nt2 + 1][1] = q3;
            }
#pragma unroll
            for (int mt = 0; mt < 4; mt++)
#pragma unroll
                for (int nt = 0; nt < 8; nt++)
                    mma_tf32(acc[mt][nt], aF[mt], bF[nt]);
        }

        if (it + 1 < nit) stage(cur ^ 1);
        __syncthreads();
    }

#pragma unroll
    for (int mt = 0; mt < 4; mt++) {
        int r0 = bm + wm + mt * 16 + (lane >> 2);
#pragma unroll
        for (int nt = 0; nt < 8; nt++) {
            int c = bn + wn + nt * 8 + ((lane & 3) << 1);
#pragma unroll
            for (int half = 0; half < 2; half++) {
                int r = r0 + half * 8;
                float v0 = acc[mt][nt][half * 2 + 0] * alpha;
                float v1 = acc[mt][nt][half * 2 + 1] * alpha;
                if (RES) {
                    v0 += R[(size_t)r * N + c];
                    v1 += R[(size_t)r * N + c + 1];
                }
                if (GELU_) { v0 = gelu_f(v0); v1 = gelu_f(v1); }
                *(float2*)(C + (size_t)r * N + c) = make_float2(v0, v1);
            }
        }
    }
}

// ---------------------------------------------------------------------------
// Wide TF32 GEMM: 256 threads, tile 128(M) x 256(N), BK=16, double-buffered.
// Warp tile 64x64 (8 warps: 2m x 4n). 2x B reuse and 2x flops per sync vs
// narrow. Used for QKV (fused), W1, and the logits GEMM.
//   BT=true : B is [N,K] row-major (A @ B^T), N guarded.
//   BT=false: B is [K,N] row-major.
// Dynamic smem: (2560 + 5120) floats * 2 buffers = 61,440 bytes.
// ---------------------------------------------------------------------------
#define WSMEM_BYTES (15360 * 4)

template <bool BT, bool RES, bool GELU_>
__device__ __forceinline__ void gemm_wide_core(const float* __restrict__ A,
                                               const float* __restrict__ B,
                                               float* __restrict__ C,
                                               const float* __restrict__ R,
                                               int N, int K, float alpha,
                                               int bm, int bn) {
    extern __shared__ float wsm[];
    const int tid = threadIdx.x;
    const int lane = tid & 31;
    const int warp = tid >> 5;
    const int wm = (warp & 1) * 64;
    const int wn = (warp >> 1) * 64;

    float acc[4][8][4];
#pragma unroll
    for (int i = 0; i < 4; i++)
#pragma unroll
        for (int j = 0; j < 8; j++)
#pragma unroll
            for (int t = 0; t < 4; t++) acc[i][j][t] = 0.f;

    const uint32_t sbase = smem_u32(wsm);
    // layout: A buf0 [0,2560), A buf1 [2560,5120), B buf0 [5120,10240), B buf1 [10240,15360)
    float4 ra[2], rb[4];

    auto load_gl = [&](int k0) {
#pragma unroll
        for (int i = 0; i < 2; i++) {
            int slot = tid + (i << 8);
            int row = slot >> 2, kq = (slot & 3) << 2;
            ra[i] = *(const float4*)(A + (size_t)(bm + row) * K + k0 + kq);
        }
        if (BT) {
#pragma unroll
            for (int i = 0; i < 4; i++) {
                int slot = tid + (i << 8);
                int n = slot >> 2, kq = (slot & 3) << 2;
                rb[i] = (bn + n < N)
                    ? *(const float4*)(B + (size_t)(bn + n) * K + k0 + kq)
                    : make_float4(0.f, 0.f, 0.f, 0.f);
            }
        } else {
#pragma unroll
            for (int i = 0; i < 4; i++) {
                int slot = tid + (i << 8);
                int kr = slot >> 6, nq = (slot & 63) << 2;
                rb[i] = *(const float4*)(B + (size_t)(k0 + kr) * N + bn + nq);
            }
        }
    };
    auto stage = [&](int buf) {
        float* sA = wsm + buf * 2560;
        float* sB = wsm + 5120 + buf * 5120;
#pragma unroll
        for (int i = 0; i < 2; i++) {
            int slot = tid + (i << 8);
            int row = slot >> 2, kq = (slot & 3) << 2;
            float4 va;
            va.x = to_tf32(ra[i].x); va.y = to_tf32(ra[i].y);
            va.z = to_tf32(ra[i].z); va.w = to_tf32(ra[i].w);
            *(float4*)(sA + row * LDW + kq) = va;
        }
        if (BT) {
#pragma unroll
            for (int i = 0; i < 4; i++) {
                int slot = tid + (i << 8);
                int n = slot >> 2, kq = (slot & 3) << 2;
                float4 vb;
                vb.x = to_tf32(rb[i].x); vb.y = to_tf32(rb[i].y);
                vb.z = to_tf32(rb[i].z); vb.w = to_tf32(rb[i].w);
                *(float4*)(sB + n * LDW + kq) = vb;
            }
        } else {
#pragma unroll
            for (int i = 0; i < 4; i++) {
                int slot = tid + (i << 8);
                int kr = slot >> 6, nq = (slot & 63) << 2;
                sB[(nq + 0) * LDW + kr] = to_tf32(rb[i].x);
                sB[(nq + 1) * LDW + kr] = to_tf32(rb[i].y);
                sB[(nq + 2) * LDW + kr] = to_tf32(rb[i].z);
                sB[(nq + 3) * LDW + kr] = to_tf32(rb[i].w);
            }
        }
    };

    const int nit = K >> 4;
    load_gl(0);
    stage(0);
    __syncthreads();

    const int lr = lane & 7;
    const int sel = lane >> 3;
    const int arof = (sel & 1) ? 8 : 0;
    const int acof = (sel & 2) ? 4 : 0;
    const int brof = (sel & 2) ? 8 : 0;
    const int bcof = (sel & 1) ? 4 : 0;

    for (int it = 0; it < nit; ++it) {
        int cur = it & 1;
        if (it + 1 < nit) load_gl((it + 1) << 4);

        uint32_t aU = sbase + (cur * 2560) * 4;
        uint32_t bU = sbase + ((5120 + cur * 5120)) * 4;

#pragma unroll
        for (int kk8 = 0; kk8 < 2; ++kk8) {
            int kk = kk8 << 3;
            uint32_t aF[4][4], bF[8][2];
#pragma unroll
            for (int mt = 0; mt < 4; mt++) {
                uint32_t ad = aU + ((wm + mt * 16 + lr + arof) * LDW + kk + acof) * 4;
                ldmat_x4(aF[mt][0], aF[mt][1], aF[mt][2], aF[mt][3], ad);
            }
#pragma unroll
            for (int nt2 = 0; nt2 < 4; nt2++) {
                uint32_t bd = bU + ((wn + nt2 * 16 + lr + brof) * LDW + kk + bcof) * 4;
                uint32_t q0, q1, q2, q3;
                ldmat_x4(q0, q1, q2, q3, bd);
                bF[2 * nt2][0] = q0;     bF[2 * nt2][1] = q1;
                bF[2 * nt2 + 1][0] = q2; bF[2 * nt2 + 1][1] = q3;
            }
#pragma unroll
            for (int mt = 0; mt < 4; mt++)
#pragma unroll
                for (int nt = 0; nt < 8; nt++)
                    mma_tf32(acc[mt][nt], aF[mt], bF[nt]);
        }

        if (it + 1 < nit) stage(cur ^ 1);
        __syncthreads();
    }

    // Epilogue
#pragma unroll
    for (int mt = 0; mt < 4; mt++) {
        int r0 = bm + wm + mt * 16 + (lane >> 2);
#pragma unroll
        for (int nt = 0; nt < 8; nt++) {
            int c = bn + wn + nt * 8 + ((lane & 3) << 1);
#pragma unroll
            for (int half = 0; half < 2; half++) {
                int r = r0 + half * 8;
                float v0 = acc[mt][nt][half * 2 + 0] * alpha;
                float v1 = acc[mt][nt][half * 2 + 1] * alpha;
                if (RES) {
                    v0 += R[(size_t)r * N + c];
                    v1 += R[(size_t)r * N + c + 1];
                }
                if (GELU_) { v0 = gelu_f(v0); v1 = gelu_f(v1); }
                if (BT) {
                    if (c < N)     C[(size_t)r * N + c] = v0;
                    if (c + 1 < N) C[(size_t)r * N + c + 1] = v1;
                } else {
                    *(float2*)(C + (size_t)r * N + c) = make_float2(v0, v1);
                }
            }
        }
    }
}

template <bool BT, bool RES, bool GELU_>
__global__ __launch_bounds__(256, 1) void gemm_wide(const float* __restrict__ A,
                                                    const float* __restrict__ B,
                                                    float* __restrict__ C,
                                                    const float* __restrict__ R,
                                                    int N, int K, float alpha) {
    gemm_wide_core<BT, RES, GELU_>(A, B, C, R, N, K, alpha,
                                   blockIdx.y * 128, blockIdx.x * 256);
}

// Fused QKV (wide): grid.z selects projection -> 3*16*3 = 144 blocks
__global__ __launch_bounds__(256, 1) void qkv_wide(const float* __restrict__ h,
                                                   const float* __restrict__ wq,
                                                   const float* __restrict__ wk,
                                                   const float* __restrict__ wv,
                                                   float* __restrict__ q,
                                                   float* __restrict__ k,
                                                   float* __restrict__ v) {
    const float* B;
    float* C;
    float alpha;
    if (blockIdx.z == 0)      { B = wq; C = q; alpha = 0.125f; }
    else if (blockIdx.z == 1) { B = wk; C = k; alpha = 1.0f; }
    else                      { B = wv; C = v; alpha = 1.0f; }
    gemm_wide_core<false, false, false>(h, B, C, nullptr, DMODEL, DMODEL, alpha,
                                        blockIdx.y * 128, blockIdx.x * 256);
}

// ---------------------------------------------------------------------------
// Launch
// ---------------------------------------------------------------------------
extern "C" void kernel_launch(void* const* d_in, const int* in_sizes, int n_in,
                              void* d_out, int out_size) {
    (void)in_sizes; (void)n_in; (void)out_size;
    const int*   tokens = (const int*)d_in[0];
    const float* embed  = (const float*)d_in[1];
    const float* pos    = (const float*)d_in[2];
    const float* Wq     = (const float*)d_in[3];
    const float* Wk     = (const float*)d_in[4];
    const float* Wv     = (const float*)d_in[5];
    const float* Wo     = (const float*)d_in[6];
    const float* Ln1    = (const float*)d_in[7];
    const float* W1     = (const float*)d_in[8];
    const float* W2     = (const float*)d_in[9];
    const float* Ln2    = (const float*)d_in[10];
    const float* OutLn  = (const float*)d_in[11];
    float* out = (float*)d_out;

    float *x, *h, *q, *k, *v, *att, *ffn;
    cudaGetSymbolAddress((void**)&x,   g_x);
    cudaGetSymbolAddress((void**)&h,   g_h);
    cudaGetSymbolAddress((void**)&q,   g_q);
    cudaGetSymbolAddress((void**)&k,   g_k);
    cudaGetSymbolAddress((void**)&v,   g_v);
    cudaGetSymbolAddress((void**)&att, g_att);
    cudaGetSymbolAddress((void**)&ffn, g_ffn);

    // >48KB dynamic smem opt-in for wide kernels (host-side attribute, graph-safe)
    cudaFuncSetAttribute(gemm_wide<false, false, true>,
                         cudaFuncAttributeMaxDynamicSharedMemorySize, WSMEM_BYTES);
    cudaFuncSetAttribute(gemm_wide<true, false, false>,
                         cudaFuncAttributeMaxDynamicSharedMemorySize, WSMEM_BYTES);
    cudaFuncSetAttribute(qkv_wide,
                         cudaFuncAttributeMaxDynamicSharedMemorySize, WSMEM_BYTES);

    embed_kernel<<<SEQ_L, 256>>>(tokens, embed, pos, x);

    dim3 grid_qkv(DMODEL / 256, SEQ_L / 128, 3);          // 3 x 16 x 3
    dim3 grid_dd(DMODEL / 128, SEQ_L / 128);              // 6 x 16 (narrow)
    dim3 grid_df(FFDIM / 256, SEQ_L / 128);               // 12 x 16 (wide)
    dim3 grid_dv((VOCAB + 255) / 256, SEQ_L / 128);       // 197 x 16 (wide)
    dim3 grid_attn(SEQ_L / 64, NHEAD);

    for (int layer = 0; layer < NLAYER; layer++) {
        const float* wq = Wq + (size_t)layer * DMODEL * DMODEL;
        const float* wk = Wk + (size_t)layer * DMODEL * DMODEL;
        const float* wv = Wv + (size_t)layer * DMODEL * DMODEL;
        const float* wo = Wo + (size_t)layer * DMODEL * DMODEL;
        const float* g1 = Ln1 + (size_t)layer * DMODEL;
        const float* w1 = W1 + (size_t)layer * DMODEL * FFDIM;
        const float* w2 = W2 + (size_t)layer * FFDIM * DMODEL;
        const float* g2 = Ln2 + (size_t)layer * DMODEL;

        ln_kernel<<<SEQ_L, 256>>>(x, g1, h);
        qkv_wide<<<grid_qkv, 256, WSMEM_BYTES>>>(h, wq, wk, wv, q, k, v);
        flash_attn<<<grid_attn, 128>>>(q, k, v, att);
        gemm_narrow<true, false><<<grid_dd, 128>>>(att, wo, x, x,
            DMODEL, DMODEL, 1.0f);
        ln_kernel<<<SEQ_L, 256>>>(x, g2, h);
        gemm_wide<false, false, true><<<grid_df, 256, WSMEM_BYTES>>>(
            h, w1, ffn, nullptr, FFDIM, DMODEL, 1.0f);
        gemm_narrow<true, false><<<grid_dd, 128>>>(ffn, w2, x, x,
            DMODEL, FFDIM, 1.0f);
    }

    ln_kernel<<<SEQ_L, 256>>>(x, OutLn, h);
    gemm_wide<true, false, false><<<grid_dv, 256, WSMEM_BYTES>>>(
        h, embed, out, nullptr, VOCAB, DMODEL, 1.0f);
}

// round 13
// speedup vs baseline: 1.2925x; 1.2925x over previous
#include <cuda_runtime.h>
#include <cstdint>

// Problem dims
#define SEQ_L   2048
#define DMODEL  768
#define NHEAD   12
#define DHEAD   64
#define FFDIM   3072
#define VOCAB   50257
#define NLAYER  4

// ---------------------------------------------------------------------------
// Device-global scratch (no allocations allowed)
// ---------------------------------------------------------------------------
__device__ float g_x  [SEQ_L * DMODEL];
__device__ float g_h  [SEQ_L * DMODEL];
__device__ float g_q  [SEQ_L * DMODEL];
__device__ float g_k  [SEQ_L * DMODEL];
__device__ float g_v  [SEQ_L * DMODEL];
__device__ float g_att[SEQ_L * DMODEL];
__device__ float g_ffn[SEQ_L * FFDIM];

// ---------------------------------------------------------------------------
// Helpers
// ---------------------------------------------------------------------------
__device__ __forceinline__ float warp_reduce_sum(float v) {
#pragma unroll
    for (int o = 16; o > 0; o >>= 1) v += __shfl_xor_sync(0xffffffffu, v, o);
    return v;
}
__device__ __forceinline__ float gelu_f(float x) {
    float x3 = x * x * x;
    return 0.5f * x * (1.0f + tanhf(0.7978845608028654f * (x + 0.044715f * x3)));
}
__device__ __forceinline__ float to_tf32(float x) {
    float y;
    asm("cvt.rna.tf32.f32 %0, %1;" : "=f"(y) : "f"(x));
    return y;
}
__device__ __forceinline__ uint32_t smem_u32(const void* p) {
    uint32_t a;
    asm("{ .reg .u64 t; cvta.to.shared.u64 t, %1; cvt.u32.u64 %0, t; }"
        : "=r"(a) : "l"(p));
    return a;
}
__device__ __forceinline__ void ldmat_x4(uint32_t& r0, uint32_t& r1,
                                         uint32_t& r2, uint32_t& r3,
                                         uint32_t addr) {
    asm volatile("ldmatrix.sync.aligned.m8n8.x4.shared.b16 {%0,%1,%2,%3}, [%4];"
                 : "=r"(r0), "=r"(r1), "=r"(r2), "=r"(r3) : "r"(addr));
}
__device__ __forceinline__ void mma_tf32(float* c, const uint32_t* a,
                                         const uint32_t* b) {
    asm volatile(
        "mma.sync.aligned.m16n8k8.row.col.f32.tf32.tf32.f32 "
        "{%0,%1,%2,%3},{%4,%5,%6,%7},{%8,%9},{%0,%1,%2,%3};"
        : "+f"(c[0]), "+f"(c[1]), "+f"(c[2]), "+f"(c[3])
        : "r"(a[0]), "r"(a[1]), "r"(a[2]), "r"(a[3]), "r"(b[0]), "r"(b[1]));
}

// ---------------------------------------------------------------------------
// Embedding
// ---------------------------------------------------------------------------
__global__ void embed_kernel(const int* __restrict__ tokens,
                             const float* __restrict__ embed,
                             const float* __restrict__ pos,
                             float* __restrict__ x) {
    int l = blockIdx.x;
    int t = tokens[l];
    const float* er = embed + (size_t)t * DMODEL;
    const float* pr = pos + (size_t)l * DMODEL;
    float* xr = x + (size_t)l * DMODEL;
    for (int d = threadIdx.x; d < DMODEL; d += blockDim.x)
        xr[d] = er[d] + pr[d];
}

// ---------------------------------------------------------------------------
// LayerNorm
// ---------------------------------------------------------------------------
__global__ void ln_kernel(const float* __restrict__ x,
                          const float* __restrict__ gamma,
                          float* __restrict__ out) {
    int l = blockIdx.x;
    const float* row = x + (size_t)l * DMODEL;
    __shared__ float sb_s[8];
    __shared__ float sb_ss[8];
    __shared__ float s_mean, s_rstd;

    float s = 0.f, ss = 0.f;
    for (int d = threadIdx.x; d < DMODEL; d += blockDim.x) {
        float v = row[d];
        s += v; ss += v * v;
    }
    s = warp_reduce_sum(s);
    ss = warp_reduce_sum(ss);
    int warp = threadIdx.x >> 5;
    if ((threadIdx.x & 31) == 0) { sb_s[warp] = s; sb_ss[warp] = ss; }
    __syncthreads();
    if (threadIdx.x == 0) {
        float ts = 0.f, tss = 0.f;
        for (int i = 0; i < 8; i++) { ts += sb_s[i]; tss += sb_ss[i]; }
        float mean = ts * (1.0f / DMODEL);
        float var = tss * (1.0f / DMODEL) - mean * mean;
        s_mean = mean;
        s_rstd = rsqrtf(var + 1e-6f);
    }
    __syncthreads();
    float mean = s_mean, rstd = s_rstd;
    float* o = out + (size_t)l * DMODEL;
    for (int d = threadIdx.x; d < DMODEL; d += blockDim.x)
        o[d] = (row[d] - mean) * rstd * gamma[d];
}

// ---------------------------------------------------------------------------
// Flash attention (validated R4, unchanged)
// ---------------------------------------------------------------------------
#define ALD 68

__global__ __launch_bounds__(128) void flash_attn(const float* __restrict__ q,
                                                  const float* __restrict__ k,
                                                  const float* __restrict__ v,
                                                  float* __restrict__ o) {
    const int qb = 31 - blockIdx.x;
    const int h = blockIdx.y;
    const int tid = threadIdx.x;
    const int lane = tid & 31;
    const int warp = tid >> 5;

    __shared__ float sA[64 * ALD];
    __shared__ float sVt[64 * ALD];
    const uint32_t sAu = smem_u32(sA);
    const uint32_t sVu = smem_u32(sVt);

    const int lr = lane & 7;
    const int sel = lane >> 3;
    const int arof = (sel & 1) ? 8 : 0;
    const int acof = (sel & 2) ? 4 : 0;
    const int brof = (sel & 2) ? 8 : 0;
    const int bcof = (sel & 1) ? 4 : 0;

    {
        const float* qp = q + (size_t)(qb * 64) * DMODEL + h * DHEAD;
#pragma unroll
        for (int i = 0; i < 8; i++) {
            int qi = tid + i * 128;
            int row = qi >> 4, c4 = (qi & 15) << 2;
            float4 vq = *(const float4*)(qp + (size_t)row * DMODEL + c4);
            vq.x = to_tf32(vq.x); vq.y = to_tf32(vq.y);
            vq.z = to_tf32(vq.z); vq.w = to_tf32(vq.w);
            *(float4*)(sA + row * ALD + c4) = vq;
        }
    }
    __syncthreads();
    uint32_t qF[8][4];
#pragma unroll
    for (int kk = 0; kk < 8; kk++) {
        uint32_t ad = sAu + ((warp * 16 + lr + arof) * ALD + kk * 8 + acof) * 4;
        ldmat_x4(qF[kk][0], qF[kk][1], qF[kk][2], qF[kk][3], ad);
    }

    float m0 = -1e30f, m1 = -1e30f, l0 = 0.f, l1 = 0.f;
    float oacc[8][4];
#pragma unroll
    for (int nt = 0; nt < 8; nt++)
#pragma unroll
        for (int c = 0; c < 4; c++) oacc[nt][c] = 0.f;

    const int ntiles = qb + 1;
    for (int t = 0; t < ntiles; t++) {
        const float* kp = k + (size_t)(t * 64) * DMODEL + h * DHEAD;
        const float* vp = v + (size_t)(t * 64) * DMODEL + h * DHEAD;
        float4 kreg[8];
#pragma unroll
        for (int i = 0; i < 8; i++) {
            int qi = tid + i * 128;
            int row = qi >> 4, c4 = (qi & 15) << 2;
            kreg[i] = *(const float4*)(kp + (size_t)row * DMODEL + c4);
        }
        float4 vreg[2][4];
#pragma unroll
        for (int ii = 0; ii < 2; ii++) {
            int tile = tid + ii * 128;
            int ks = tile >> 4, ds = tile & 15;
#pragma unroll
            for (int r = 0; r < 4; r++)
                vreg[ii][r] = *(const float4*)(vp + (size_t)(ks * 4 + r) * DMODEL + ds * 4);
        }

        __syncthreads();

#pragma unroll
        for (int i = 0; i < 8; i++) {
            int qi = tid + i * 128;
            int row = qi >> 4, c4 = (qi & 15) << 2;
            float4 vk = kreg[i];
            vk.x = to_tf32(vk.x); vk.y = to_tf32(vk.y);
            vk.z = to_tf32(vk.z); vk.w = to_tf32(vk.w);
            *(float4*)(sA + row * ALD + c4) = vk;
        }
#pragma unroll
        for (int ii = 0; ii < 2; ii++) {
            int tile = tid + ii * 128;
            int ks = tile >> 4, ds = tile & 15;
            float4 r0 = vreg[ii][0], r1 = vreg[ii][1];
            float4 r2 = vreg[ii][2], r3 = vreg[ii][3];
            float4 t0 = make_float4(to_tf32(r0.x), to_tf32(r1.x), to_tf32(r2.x), to_tf32(r3.x));
            float4 t1 = make_float4(to_tf32(r0.y), to_tf32(r1.y), to_tf32(r2.y), to_tf32(r3.y));
            float4 t2 = make_float4(to_tf32(r0.z), to_tf32(r1.z), to_tf32(r2.z), to_tf32(r3.z));
            float4 t3 = make_float4(to_tf32(r0.w), to_tf32(r1.w), to_tf32(r2.w), to_tf32(r3.w));
            *(float4*)(sVt + (ds * 4 + 0) * ALD + ks * 4) = t0;
            *(float4*)(sVt + (ds * 4 + 1) * ALD + ks * 4) = t1;
            *(float4*)(sVt + (ds * 4 + 2) * ALD + ks * 4) = t2;
            *(float4*)(sVt + (ds * 4 + 3) * ALD + ks * 4) = t3;
        }
        __syncthreads();

        float sacc[8][4];
#pragma unroll
        for (int nt = 0; nt < 8; nt++)
#pragma unroll
            for (int c = 0; c < 4; c++) sacc[nt][c] = 0.f;
#pragma unroll
        for (int kk = 0; kk < 8; kk++) {
            uint32_t bF[8][2];
#pragma unroll
            for (int nt2 = 0; nt2 < 4; nt2++) {
                uint32_t bd = sAu + ((nt2 * 16 + lr + brof) * ALD + kk * 8 + bcof) * 4;
                uint32_t b0, b1, b2, b3;
                ldmat_x4(b0, b1, b2, b3, bd);
                bF[2 * nt2][0] = b0;     bF[2 * nt2][1] = b1;
                bF[2 * nt2 + 1][0] = b2; bF[2 * nt2 + 1][1] = b3;
            }
#pragma unroll
            for (int nt = 0; nt < 8; nt++)
                mma_tf32(sacc[nt], qF[kk], bF[nt]);
        }

        if (t == qb) {
            int r0 = warp * 16 + (lane >> 2);
#pragma unroll
            for (int nt = 0; nt < 8; nt++) {
                int kl = nt * 8 + ((lane & 3) << 1);
                if (kl > r0)         sacc[nt][0] = -1e30f;
                if (kl + 1 > r0)     sacc[nt][1] = -1e30f;
                if (kl > r0 + 8)     sacc[nt][2] = -1e30f;
                if (kl + 1 > r0 + 8) sacc[nt][3] = -1e30f;
            }
        }

        float tm0 = -1e30f, tm1 = -1e30f;
#pragma unroll
        for (int nt = 0; nt < 8; nt++) {
            tm0 = fmaxf(tm0, fmaxf(sacc[nt][0], sacc[nt][1]));
            tm1 = fmaxf(tm1, fmaxf(sacc[nt][2], sacc[nt][3]));
        }
        tm0 = fmaxf(tm0, __shfl_xor_sync(0xffffffffu, tm0, 1));
        tm0 = fmaxf(tm0, __shfl_xor_sync(0xffffffffu, tm0, 2));
        tm1 = fmaxf(tm1, __shfl_xor_sync(0xffffffffu, tm1, 1));
        tm1 = fmaxf(tm1, __shfl_xor_sync(0xffffffffu, tm1, 2));
        float nm0 = fmaxf(m0, tm0), nm1 = fmaxf(m1, tm1);
        float sc0 = __expf(m0 - nm0), sc1 = __expf(m1 - nm1);
        m0 = nm0; m1 = nm1;

        float p[8][4];
        float sum0 = 0.f, sum1 = 0.f;
#pragma unroll
        for (int nt = 0; nt < 8; nt++) {
            p[nt][0] = __expf(sacc[nt][0] - nm0);
            p[nt][1] = __expf(sacc[nt][1] - nm0);
            p[nt][2] = __expf(sacc[nt][2] - nm1);
            p[nt][3] = __expf(sacc[nt][3] - nm1);
            sum0 += p[nt][0] + p[nt][1];
            sum1 += p[nt][2] + p[nt][3];
        }
        sum0 += __shfl_xor_sync(0xffffffffu, sum0, 1);
        sum0 += __shfl_xor_sync(0xffffffffu, sum0, 2);
        sum1 += __shfl_xor_sync(0xffffffffu, sum1, 1);
        sum1 += __shfl_xor_sync(0xffffffffu, sum1, 2);
        l0 = l0 * sc0 + sum0;
        l1 = l1 * sc1 + sum1;
#pragma unroll
        for (int nt = 0; nt < 8; nt++) {
            oacc[nt][0] *= sc0; oacc[nt][1] *= sc0;
            oacc[nt][2] *= sc1; oacc[nt][3] *= sc1;
        }

        __syncthreads();

        {
            int r0 = warp * 16 + (lane >> 2);
            int cb = (lane & 3) << 1;
#pragma unroll
            for (int nt = 0; nt < 8; nt++) {
                int col = nt * 8 + cb;
                *(float2*)(sA + r0 * ALD + col) =
                    make_float2(to_tf32(p[nt][0]), to_tf32(p[nt][1]));
                *(float2*)(sA + (r0 + 8) * ALD + col) =
                    make_float2(to_tf32(p[nt][2]), to_tf32(p[nt][3]));
            }
        }
        __syncwarp();

#pragma unroll
        for (int kk = 0; kk < 8; kk++) {
            uint32_t aP[4];
            uint32_t ad = sAu + ((warp * 16 + lr + arof) * ALD + kk * 8 + acof) * 4;
            ldmat_x4(aP[0], aP[1], aP[2], aP[3], ad);
            uint32_t bF[8][2];
#pragma unroll
            for (int nt2 = 0; nt2 < 4; nt2++) {
                uint32_t bd = sVu + ((nt2 * 16 + lr + brof) * ALD + kk * 8 + bcof) * 4;
                uint32_t b0, b1, b2, b3;
                ldmat_x4(b0, b1, b2, b3, bd);
                bF[2 * nt2][0] = b0;     bF[2 * nt2][1] = b1;
                bF[2 * nt2 + 1][0] = b2; bF[2 * nt2 + 1][1] = b3;
            }
#pragma unroll
            for (int nt = 0; nt < 8; nt++)
                mma_tf32(oacc[nt], aP, bF[nt]);
        }
    }

    float inv0 = 1.0f / l0, inv1 = 1.0f / l1;
    int row0 = qb * 64 + warp * 16 + (lane >> 2);
    int cb = h * DHEAD + ((lane & 3) << 1);
#pragma unroll
    for (int nt = 0; nt < 8; nt++) {
        int col = cb + nt * 8;
        *(float2*)(o + (size_t)row0 * DMODEL + col) =
            make_float2(oacc[nt][0] * inv0, oacc[nt][1] * inv0);
        *(float2*)(o + (size_t)(row0 + 8) * DMODEL + col) =
            make_float2(oacc[nt][2] * inv1, oacc[nt][3] * inv1);
    }
}

// ---------------------------------------------------------------------------
// NN GEMM (B = [K,N] row-major weights), conflict-free staging.
// 128 threads, tile 128x128, BK=16, double-buffered.
// A staged [m][k] (LDW=20) + ldmatrix fragments (validated path).
// B staged [k][n] (LDN=136, float4 STS, NO transpose, conflict-free);
// B fragments via direct LDS.32: b0 = B[kk+lane%4][n0+lane/4], b1 at k+4.
// ---------------------------------------------------------------------------
#define LDW 20
#define LDN 136

template <bool RES, bool GELU_>
__device__ __forceinline__ void gemm_nn_core(const float* __restrict__ A,
                                             const float* __restrict__ B,
                                             float* __restrict__ C,
                                             const float* __restrict__ R,
                                             int N, int K, float alpha,
                                             int bm, int bn) {
    __shared__ float sAt[2][128 * LDW];
    __shared__ float sBt[2][16 * LDN];

    const int tid = threadIdx.x;
    const int lane = tid & 31;
    const int warp = tid >> 5;
    const int wm = (warp & 1) * 64;
    const int wn = (warp >> 1) * 64;

    float acc[4][8][4];
#pragma unroll
    for (int i = 0; i < 4; i++)
#pragma unroll
        for (int j = 0; j < 8; j++)
#pragma unroll
            for (int t = 0; t < 4; t++) acc[i][j][t] = 0.f;

    float4 ra[4], rb[4];
    auto load_gl = [&](int k0) {
#pragma unroll
        for (int i = 0; i < 4; i++) {
            int slot = tid + (i << 7);
            int row = slot >> 2, kq = (slot & 3) << 2;
            ra[i] = *(const float4*)(A + (size_t)(bm + row) * K + k0 + kq);
            int kr = slot >> 5, nq = (slot & 31) << 2;
            rb[i] = *(const float4*)(B + (size_t)(k0 + kr) * N + bn + nq);
        }
    };
    auto stage = [&](int buf) {
        float* sA = sAt[buf];
        float* sB = sBt[buf];
#pragma unroll
        for (int i = 0; i < 4; i++) {
            int slot = tid + (i << 7);
            int row = slot >> 2, kq = (slot & 3) << 2;
            float4 va;
            va.x = to_tf32(ra[i].x); va.y = to_tf32(ra[i].y);
            va.z = to_tf32(ra[i].z); va.w = to_tf32(ra[i].w);
            *(float4*)(sA + row * LDW + kq) = va;
            int kr = slot >> 5, nq = (slot & 31) << 2;
            float4 vb;
            vb.x = to_tf32(rb[i].x); vb.y = to_tf32(rb[i].y);
            vb.z = to_tf32(rb[i].z); vb.w = to_tf32(rb[i].w);
            *(float4*)(sB + kr * LDN + nq) = vb;
        }
    };

    const int nit = K >> 4;
    load_gl(0);
    stage(0);
    __syncthreads();

    const int lr = lane & 7;
    const int sel = lane >> 3;
    const int arof = (sel & 1) ? 8 : 0;
    const int acof = (sel & 2) ? 4 : 0;
    const int bk = lane & 3;       // fragment k within group
    const int bn4 = lane >> 2;     // fragment n within tile

    for (int it = 0; it < nit; ++it) {
        int cur = it & 1;
        if (it + 1 < nit) load_gl((it + 1) << 4);

        const uint32_t aU = smem_u32(sAt[cur]);
        const float* sB = sBt[cur];

#pragma unroll
        for (int kk8 = 0; kk8 < 2; ++kk8) {
            int kk = kk8 << 3;
            uint32_t aF[4][4], bF[8][2];
#pragma unroll
            for (int mt = 0; mt < 4; mt++) {
                uint32_t ad = aU + ((wm + mt * 16 + lr + arof) * LDW + kk + acof) * 4;
                ldmat_x4(aF[mt][0], aF[mt][1], aF[mt][2], aF[mt][3], ad);
            }
            const float* b0p = sB + (kk + bk) * LDN + wn + bn4;
            const float* b1p = b0p + 4 * LDN;
#pragma unroll
            for (int nt = 0; nt < 8; nt++) {
                bF[nt][0] = __float_as_uint(b0p[nt * 8]);
                bF[nt][1] = __float_as_uint(b1p[nt * 8]);
            }
#pragma unroll
            for (int mt = 0; mt < 4; mt++)
#pragma unroll
                for (int nt = 0; nt < 8; nt++)
                    mma_tf32(acc[mt][nt], aF[mt], bF[nt]);
        }

        if (it + 1 < nit) stage(cur ^ 1);
        __syncthreads();
    }

#pragma unroll
    for (int mt = 0; mt < 4; mt++) {
        int r0 = bm + wm + mt * 16 + (lane >> 2);
#pragma unroll
        for (int nt = 0; nt < 8; nt++) {
            int c = bn + wn + nt * 8 + ((lane & 3) << 1);
#pragma unroll
            for (int half = 0; half < 2; half++) {
                int r = r0 + half * 8;
                float v0 = acc[mt][nt][half * 2 + 0] * alpha;
                float v1 = acc[mt][nt][half * 2 + 1] * alpha;
                if (RES) {
                    v0 += R[(size_t)r * N + c];
                    v1 += R[(size_t)r * N + c + 1];
                }
                if (GELU_) { v0 = gelu_f(v0); v1 = gelu_f(v1); }
                *(float2*)(C + (size_t)r * N + c) = make_float2(v0, v1);
            }
        }
    }
}

template <bool RES, bool GELU_>
__global__ __launch_bounds__(128, 2) void gemm_nn(const float* __restrict__ A,
                                                  const float* __restrict__ B,
                                                  float* __restrict__ C,
                                                  const float* __restrict__ R,
                                                  int N, int K, float alpha) {
    gemm_nn_core<RES, GELU_>(A, B, C, R, N, K, alpha,
                             blockIdx.x * 128, blockIdx.y * 128);
}

// Fused QKV: grid.z selects projection (3 x 16 x 6... -> 6x16x3 = 288 blocks)
__global__ __launch_bounds__(128, 2) void qkv_nn(const float* __restrict__ h,
                                                 const float* __restrict__ wq,
                                                 const float* __restrict__ wk,
                                                 const float* __restrict__ wv,
                                                 float* __restrict__ q,
                                                 float* __restrict__ k,
                                                 float* __restrict__ v) {
    const float* B;
    float* C;
    float alpha;
    if (blockIdx.z == 0)      { B = wq; C = q; alpha = 0.125f; }
    else if (blockIdx.z == 1) { B = wk; C = k; alpha = 1.0f; }
    else                      { B = wv; C = v; alpha = 1.0f; }
    gemm_nn_core<false, false>(h, B, C, nullptr, DMODEL, DMODEL, alpha,
                               blockIdx.x * 128, blockIdx.y * 128);
}

// ---------------------------------------------------------------------------
// NT GEMM (logits): B = [N,K] row-major, C = A @ B^T. Exact R4-validated path
// (B staged [n][k] via float4, ldmatrix B fragments). Grid: x = M (fastest)
// so the 16 M-blocks sharing a B stripe run adjacently (embed streamed once).
// ---------------------------------------------------------------------------
__global__ __launch_bounds__(128, 2) void gemm_nt(const float* __restrict__ A,
                                                  const float* __restrict__ B,
                                                  float* __restrict__ C,
                                                  int N, int K) {
    __shared__ float smem[4 * 128 * LDW];
    const int tid = threadIdx.x;
    const int lane = tid & 31;
    const int warp = tid >> 5;
    const int wm = (warp & 1) * 64;
    const int wn = (warp >> 1) * 64;
    const int bm = blockIdx.x * 128;
    const int bn = blockIdx.y * 128;

    float acc[4][8][4];
#pragma unroll
    for (int i = 0; i < 4; i++)
#pragma unroll
        for (int j = 0; j < 8; j++)
#pragma unroll
            for (int t = 0; t < 4; t++) acc[i][j][t] = 0.f;

    const uint32_t sbase = smem_u32(smem);
    float4 ra[4], rb[4];

    auto load_gl = [&](int k0) {
#pragma unroll
        for (int i = 0; i < 4; i++) {
            int qidx = tid + i * 128;
            int row = qidx >> 2, kq = (qidx & 3) << 2;
            ra[i] = *(const float4*)(A + (size_t)(bm + row) * K + k0 + kq);
            int n = bn + row;
            rb[i] = (n < N) ? *(const float4*)(B + (size_t)n * K + k0 + kq)
                            : make_float4(0.f, 0.f, 0.f, 0.f);
        }
    };
    auto stage = [&](int buf) {
        float* sA = smem + buf * (128 * LDW);
        float* sB = smem + 2 * (128 * LDW) + buf * (128 * LDW);
#pragma unroll
        for (int i = 0; i < 4; i++) {
            int qidx = tid + i * 128;
            int row = qidx >> 2, kq = (qidx & 3) << 2;
            float4 va;
            va.x = to_tf32(ra[i].x); va.y = to_tf32(ra[i].y);
            va.z = to_tf32(ra[i].z); va.w = to_tf32(ra[i].w);
            *(float4*)(sA + row * LDW + kq) = va;
            float4 vb;
            vb.x = to_tf32(rb[i].x); vb.y = to_tf32(rb[i].y);
            vb.z = to_tf32(rb[i].z); vb.w = to_tf32(rb[i].w);
            *(float4*)(sB + row * LDW + kq) = vb;
        }
    };

    const int nit = K >> 4;
    load_gl(0);
    stage(0);
    __syncthreads();

    const int lr = lane & 7;
    const int sel = lane >> 3;
    const int arof = (sel & 1) ? 8 : 0;
    const int acof = (sel & 2) ? 4 : 0;
    const int brof = (sel & 2) ? 8 : 0;
    const int bcof = (sel & 1) ? 4 : 0;

    for (int it = 0; it < nit; ++it) {
        int cur = it & 1;
        if (it + 1 < nit) load_gl((it + 1) << 4);

        uint32_t aU = sbase + (cur * (128 * LDW)) * 4;
        uint32_t bU = sbase + ((2 + cur) * (128 * LDW)) * 4;

#pragma unroll
        for (int kk8 = 0; kk8 < 2; ++kk8) {
            int kk = kk8 << 3;
            uint32_t aF[4][4], bF[8][2];
#pragma unroll
            for (int mt = 0; mt < 4; mt++) {
                uint32_t ad = aU + ((wm + mt * 16 + lr + arof) * LDW + kk + acof) * 4;
                ldmat_x4(aF[mt][0], aF[mt][1], aF[mt][2], aF[mt][3], ad);
            }
#pragma unroll
            for (int nt2 = 0; nt2 < 4; nt2++) {
                uint32_t bd = bU + ((wn + nt2 * 16 + lr + brof) * LDW + kk + bcof) * 4;
                uint32_t q0, q1, q2, q3;
                ldmat_x4(q0, q1, q2, q3, bd);
                bF[2 * nt2][0] = q0;     bF[2 * nt2][1] = q1;
                bF[2 * nt2 + 1][0] = q2; bF[2 * nt2 + 1][1] = q3;
            }
#pragma unroll
            for (int mt = 0; mt < 4; mt++)
#pragma unroll
                for (int nt = 0; nt < 8; nt++)
                    mma_tf32(acc[mt][nt], aF[mt], bF[nt]);
        }

        if (it + 1 < nit) stage(cur ^ 1);
        __syncthreads();
    }

#pragma unroll
    for (int mt = 0; mt < 4; mt++) {
        int r0 = bm + wm + mt * 16 + (lane >> 2);
#pragma unroll
        for (int nt = 0; nt < 8; nt++) {
            int c = bn + wn + nt * 8 + ((lane & 3) << 1);
#pragma unroll
            for (int half = 0; half < 2; half++) {
                int r = r0 + half * 8;
                float v0 = acc[mt][nt][half * 2 + 0];
                float v1 = acc[mt][nt][half * 2 + 1];
                if (c < N)     C[(size_t)r * N + c] = v0;
                if (c + 1 < N) C[(size_t)r * N + c + 1] = v1;
            }
        }
    }
}

// ---------------------------------------------------------------------------
// Launch
// ---------------------------------------------------------------------------
extern "C" void kernel_launch(void* const* d_in, const int* in_sizes, int n_in,
                              void* d_out, int out_size) {
    (void)in_sizes; (void)n_in; (void)out_size;
    const int*   tokens = (const int*)d_in[0];
    const float* embed  = (const float*)d_in[1];
    const float* pos    = (const float*)d_in[2];
    const float* Wq     = (const float*)d_in[3];
    const float* Wk     = (const float*)d_in[4];
    const float* Wv     = (const float*)d_in[5];
    const float* Wo     = (const float*)d_in[6];
    const float* Ln1    = (const float*)d_in[7];
    const float* W1     = (const float*)d_in[8];
    const float* W2     = (const float*)d_in[9];
    const float* Ln2    = (const float*)d_in[10];
    const float* OutLn  = (const float*)d_in[11];
    float* out = (float*)d_out;

    float *x, *h, *q, *k, *v, *att, *ffn;
    cudaGetSymbolAddress((void**)&x,   g_x);
    cudaGetSymbolAddress((void**)&h,   g_h);
    cudaGetSymbolAddress((void**)&q,   g_q);
    cudaGetSymbolAddress((void**)&k,   g_k);
    cudaGetSymbolAddress((void**)&v,   g_v);
    cudaGetSymbolAddress((void**)&att, g_att);
    cudaGetSymbolAddress((void**)&ffn, g_ffn);

    embed_kernel<<<SEQ_L, 256>>>(tokens, embed, pos, x);

    dim3 grid_qkv(SEQ_L / 128, DMODEL / 128, 3);        // 16 x 6 x 3 = 288
    dim3 grid_dd(SEQ_L / 128, DMODEL / 128);            // 16 x 6
    dim3 grid_df(SEQ_L / 128, FFDIM / 128);             // 16 x 24
    dim3 grid_dv(SEQ_L / 128, (VOCAB + 127) / 128);     // 16 x 393 (M fastest)
    dim3 grid_attn(SEQ_L / 64, NHEAD);

    for (int layer = 0; layer < NLAYER; layer++) {
        const float* wq = Wq + (size_t)layer * DMODEL * DMODEL;
        const float* wk = Wk + (size_t)layer * DMODEL * DMODEL;
        const float* wv = Wv + (size_t)layer * DMODEL * DMODEL;
        const float* wo = Wo + (size_t)layer * DMODEL * DMODEL;
        const float* g1 = Ln1 + (size_t)layer * DMODEL;
        const float* w1 = W1 + (size_t)layer * DMODEL * FFDIM;
        const float* w2 = W2 + (size_t)layer * FFDIM * DMODEL;
        const float* g2 = Ln2 + (size_t)layer * DMODEL;

        ln_kernel<<<SEQ_L, 256>>>(x, g1, h);
        qkv_nn<<<grid_qkv, 128>>>(h, wq, wk, wv, q, k, v);
        flash_attn<<<grid_attn, 128>>>(q, k, v, att);
        gemm_nn<true, false><<<grid_dd, 128>>>(att, wo, x, x,
            DMODEL, DMODEL, 1.0f);
        ln_kernel<<<SEQ_L, 256>>>(x, g2, h);
        gemm_nn<false, true><<<grid_df, 128>>>(h, w1, ffn, nullptr,
            FFDIM, DMODEL, 1.0f);
        gemm_nn<true, false><<<grid_dd, 128>>>(ffn, w2, x, x,
            DMODEL, FFDIM, 1.0f);
    }

    ln_kernel<<<SEQ_L, 256>>>(x, OutLn, h);
    gemm_nt<<<grid_dv, 128>>>(h, embed, out, VOCAB, DMODEL);
}